// round 8
// baseline (speedup 1.0000x reference)
#include <cuda_runtime.h>
#include <math.h>
#include <stdint.h>

// ---------------------------------------------------------------------------
// GraphProjection: 80000 points, 3 cameras, feature pyramid (64/128/256/512 ch)
// out[p] = [coord(3) | max over views(960) | mean(960) | std(960)] -> 2883 f32
// Round 8: keep shifted-window aligned STG.128 (R7 cut L1-active 137->103us);
//          fix the occupancy loss: __launch_bounds__(256,8) (<=32 regs),
//          32-bit indexing, leaner divergent paths.
// ---------------------------------------------------------------------------

#define MAX_N 80000
#define OUT_STRIDE 2883

__device__ int g_off[MAX_N * 12];   // [point][view*4 + scale] flat float offset

struct CamData {
    float B0[9];     // inv(c0^T)
    float c[3][9];   // per-view rotation rows (X,Y,Z normalized)
    float o[3][3];   // per-view camera origin (unnormalized Z)
};

// --- camera matrix, mirroring jnp fp32 op order -----------------------------
__device__ __forceinline__ void cam_mat(const float* prm, float* Crow, float* O) {
    const float PI = 3.14159265358979323846f;
    float theta = prm[0] * PI / 180.0f;
    float e     = prm[1] * PI / 180.0f;
    float camy  = prm[3] * sinf(e);
    float lens  = prm[3] * cosf(e);
    float camx  = lens * cosf(theta);
    float camz  = lens * sinf(theta);

    float Zv[3] = { camx, camy, camz };
    float Yv[3] = { camy * cosf(theta + PI), lens, camy * sinf(theta + PI) };
    float Xv[3] = { Yv[1]*Zv[2] - Yv[2]*Zv[1],
                    Yv[2]*Zv[0] - Yv[0]*Zv[2],
                    Yv[0]*Zv[1] - Yv[1]*Zv[0] };

    float nx = sqrtf(Xv[0]*Xv[0] + Xv[1]*Xv[1] + Xv[2]*Xv[2]);
    float ny = sqrtf(Yv[0]*Yv[0] + Yv[1]*Yv[1] + Yv[2]*Yv[2]);
    float nz = sqrtf(Zv[0]*Zv[0] + Zv[1]*Zv[1] + Zv[2]*Zv[2]);
    for (int k = 0; k < 3; k++) {
        Crow[0*3 + k] = __fdiv_rn(Xv[k], nx);
        Crow[1*3 + k] = __fdiv_rn(Yv[k], ny);
        Crow[2*3 + k] = __fdiv_rn(Zv[k], nz);
        O[k] = Zv[k];
    }
}

// --- kernel A: per-block camera setup (incl. DP inverse) + per-point offsets
__global__ __launch_bounds__(256)
void proj_kernel(const float* __restrict__ coord,
                 const float* __restrict__ cams, int N) {
    __shared__ CamData cam;

    if (threadIdx.x == 0) {
        for (int i = 0; i < 3; i++)
            cam_mat(cams + i * 5, cam.c[i], cam.o[i]);

        double M[3][3];
        for (int r = 0; r < 3; r++)
            for (int k = 0; k < 3; k++)
                M[r][k] = (double)cam.c[0][k*3 + r];

        double det = M[0][0]*(M[1][1]*M[2][2] - M[1][2]*M[2][1])
                   - M[0][1]*(M[1][0]*M[2][2] - M[1][2]*M[2][0])
                   + M[0][2]*(M[1][0]*M[2][1] - M[1][1]*M[2][0]);
        double inv[3][3];
        inv[0][0] =  (M[1][1]*M[2][2] - M[1][2]*M[2][1]) / det;
        inv[0][1] =  (M[0][2]*M[2][1] - M[0][1]*M[2][2]) / det;
        inv[0][2] =  (M[0][1]*M[1][2] - M[0][2]*M[1][1]) / det;
        inv[1][0] =  (M[1][2]*M[2][0] - M[1][0]*M[2][2]) / det;
        inv[1][1] =  (M[0][0]*M[2][2] - M[0][2]*M[2][0]) / det;
        inv[1][2] =  (M[0][2]*M[1][0] - M[0][0]*M[1][2]) / det;
        inv[2][0] =  (M[1][0]*M[2][1] - M[1][1]*M[2][0]) / det;
        inv[2][1] =  (M[0][1]*M[2][0] - M[0][0]*M[2][1]) / det;
        inv[2][2] =  (M[0][0]*M[1][1] - M[0][1]*M[1][0]) / det;
        for (int k = 0; k < 3; k++)
            for (int j = 0; j < 3; j++)
                cam.B0[k*3 + j] = (float)inv[k][j];
    }
    __syncthreads();

    int p = blockIdx.x * blockDim.x + threadIdx.x;
    if (p >= N) return;

    float x = coord[p*3 + 0];
    float y = coord[p*3 + 1];
    float z = coord[p*3 + 2];

    float po[3];
    #pragma unroll
    for (int j = 0; j < 3; j++)
        po[j] = x * cam.B0[0*3 + j] + y * cam.B0[1*3 + j]
              + z * cam.B0[2*3 + j] + cam.o[0][j];

    const int   ds[4] = { 56, 28, 14, 7 };
    const int   Cs[4] = { 64, 128, 256, 512 };
    const float qi[4] = { 0.25f, 0.125f, 0.0625f, 0.03125f };  // d/224 exact pow2

    int off[12];
    #pragma unroll
    for (int i = 0; i < 3; i++) {
        float vx = po[0] - cam.o[i][0];
        float vy = po[1] - cam.o[i][1];
        float vz = po[2] - cam.o[i][2];
        const float* C = cam.c[i];
        float X  = vx*C[0] + vy*C[1] + vz*C[2];
        float Y  = vx*C[3] + vy*C[4] + vz*C[5];
        float Zc = vx*C[6] + vy*C[7] + vz*C[8];

        float negz = -Zc;
        float h = __fdiv_rn(248.0f * (-Y), negz) + 112.0f;
        float w = __fdiv_rn(248.0f * X,    negz) + 112.0f;
        h = fminf(fmaxf(h, 0.0f), 223.0f);
        w = fminf(fmaxf(w, 0.0f), 223.0f);

        #pragma unroll
        for (int s = 0; s < 4; s++) {
            int ih = (int)(h * qi[s]);
            int iw = (int)(w * qi[s]);
            off[i*4 + s] = (ih * ds[s] + iw) * Cs[s];
        }
    }
    int4* dst = reinterpret_cast<int4*>(g_off + p*12);
    dst[0] = make_int4(off[0], off[1], off[2],  off[3]);
    dst[1] = make_int4(off[4], off[5], off[6],  off[7]);
    dst[2] = make_int4(off[8], off[9], off[10], off[11]);
}

// channel -> (feature tensor, scale idx, local channel)
__device__ __forceinline__ void map_ch(int c, const float* f1, const float* f2,
                                       const float* f3, const float* f4,
                                       const float*& f, int& s, int& cl) {
    if (c < 64)       { s = 0; f = f1; cl = c; }
    else if (c < 192) { s = 1; f = f2; cl = c - 64; }
    else if (c < 448) { s = 2; f = f3; cl = c - 192; }
    else              { s = 3; f = f4; cl = c - 448; }
}

// select 4-wide window starting at shift sh from two adjacent quads
__device__ __forceinline__ void shiftwin(int sh, float4 A, float4 B, float w[4]) {
    switch (sh) {
        case 0:  w[0]=A.x; w[1]=A.y; w[2]=A.z; w[3]=A.w; break;
        case 1:  w[0]=A.y; w[1]=A.z; w[2]=A.w; w[3]=B.x; break;
        case 2:  w[0]=A.z; w[1]=A.w; w[2]=B.x; w[3]=B.y; break;
        default: w[0]=A.w; w[1]=B.x; w[2]=B.y; w[3]=B.z; break;
    }
}

// --- kernel B: shifted-window gather, aligned STG.128, high occupancy -------
__global__ __launch_bounds__(256, 8)
void gather_kernel(const float* __restrict__ f1, const float* __restrict__ f2,
                   const float* __restrict__ f3, const float* __restrict__ f4,
                   const float* __restrict__ coord, float* __restrict__ out) {
    unsigned p = blockIdx.x;
    int t = threadIdx.x;

    __shared__ int soff[12];
    if (t < 12) soff[t] = g_off[p*12 + t];
    __syncthreads();

    unsigned g = p * (unsigned)OUT_STRIDE;          // < 2^31, 32-bit math
    int sh = (int)((4u - ((g + 3u) & 3u)) & 3u);    // g+3+sh ≡ 0 (mod 4)

    if (t < 240) {
        int c4 = 4 * t;
        bool store_ok = (sh == 0) | (t < 239);

        const float *fa;
        int sa, cla;
        map_ch(c4, f1, f2, f3, f4, fa, sa, cla);

        float4 A0 = __ldg(reinterpret_cast<const float4*>(fa + soff[0 + sa] + cla));
        float4 A1 = __ldg(reinterpret_cast<const float4*>(fa + soff[4 + sa] + cla));
        float4 A2 = __ldg(reinterpret_cast<const float4*>(fa + soff[8 + sa] + cla));

        float4 B0 = make_float4(0,0,0,0), B1 = B0, B2 = B0;
        if (sh && store_ok) {
            const float *fb; int sb, clb;
            map_ch(c4 + 4, f1, f2, f3, f4, fb, sb, clb);
            B0 = __ldg(reinterpret_cast<const float4*>(fb + soff[0 + sb] + clb));
            B1 = __ldg(reinterpret_cast<const float4*>(fb + soff[4 + sb] + clb));
            B2 = __ldg(reinterpret_cast<const float4*>(fb + soff[8 + sb] + clb));
        }

        float av[4], bv[4], dv[4];
        shiftwin(sh, A0, B0, av);
        shiftwin(sh, A1, B1, bv);
        shiftwin(sh, A2, B2, dv);

        float mxv[4], mnv[4], sdv[4];
        #pragma unroll
        for (int k = 0; k < 4; k++) {
            float aa = av[k], bb = bv[k], dd = dv[k];
            mxv[k] = fmaxf(aa, fmaxf(bb, dd));
            float mn = (aa + bb + dd) * (1.0f / 3.0f);
            mnv[k] = mn;
            float da = aa - mn, db = bb - mn, dc = dd - mn;
            sdv[k] = sqrtf((da*da + db*db + dc*dc) * (1.0f / 3.0f));
        }

        if (store_ok) {
            float* base = out + (g + 3u + (unsigned)(sh + c4));
            *reinterpret_cast<float4*>(base)        = make_float4(mxv[0], mxv[1], mxv[2], mxv[3]);
            *reinterpret_cast<float4*>(base + 960)  = make_float4(mnv[0], mnv[1], mnv[2], mnv[3]);
            *reinterpret_cast<float4*>(base + 1920) = make_float4(sdv[0], sdv[1], sdv[2], sdv[3]);
        }
    } else {
        int h = t - 240;                       // 0..15
        if (sh && h < 4) {
            // edge channels: head [0, sh), tail [sh+956, 960)
            int ch = (h < sh) ? h : (956 + sh + (h - sh));
            const float* f; int ss, cl;
            map_ch(ch, f1, f2, f3, f4, f, ss, cl);
            float a = __ldg(f + soff[0 + ss] + cl);
            float b = __ldg(f + soff[4 + ss] + cl);
            float d = __ldg(f + soff[8 + ss] + cl);
            float mx = fmaxf(a, fmaxf(b, d));
            float mn = (a + b + d) * (1.0f / 3.0f);
            float da = a - mn, db = b - mn, dc = d - mn;
            float sd = sqrtf((da*da + db*db + dc*dc) * (1.0f / 3.0f));
            out[g + 3u + (unsigned)ch]    = mx;
            out[g + 963u + (unsigned)ch]  = mn;
            out[g + 1923u + (unsigned)ch] = sd;
        }
        if (h >= 8 && h < 11)                  // coord passthrough
            out[g + (unsigned)(h - 8)] = __ldg(coord + p*3 + (h - 8));
    }
}

extern "C" void kernel_launch(void* const* d_in, const int* in_sizes, int n_in,
                              void* d_out, int out_size) {
    const float* coord = (const float*)d_in[0];
    const float* cams  = (const float*)d_in[1];
    const float* f1    = (const float*)d_in[2];
    const float* f2    = (const float*)d_in[3];
    const float* f3    = (const float*)d_in[4];
    const float* f4    = (const float*)d_in[5];
    float* out = (float*)d_out;

    int N = in_sizes[0] / 3;

    proj_kernel<<<(N + 255) / 256, 256>>>(coord, cams, N);
    gather_kernel<<<N, 256>>>(f1, f2, f3, f4, coord, out);
}

// round 9
// speedup vs baseline: 1.1082x; 1.1082x over previous
#include <cuda_runtime.h>
#include <math.h>
#include <stdint.h>

// ---------------------------------------------------------------------------
// GraphProjection: 80000 points, 3 cameras, feature pyramid (64/128/256/512 ch)
// out[p] = [coord(3) | max over views(960) | mean(960) | std(960)] -> 2883 f32
// Round 9: shifted-window aligned STG.128 (R7 structure) with the neighbor
//          quad obtained by __shfl_down(1) instead of a second LDG -> low
//          register pressure (no spills), fewer instructions, fewer wavefronts.
//          Lane 31 of each warp (cross-warp neighbor) does a predicated load.
// ---------------------------------------------------------------------------

#define MAX_N 80000
#define OUT_STRIDE 2883

__device__ int g_off[MAX_N * 12];   // [point][view*4 + scale] flat float offset

struct CamData {
    float B0[9];     // inv(c0^T)
    float c[3][9];   // per-view rotation rows (X,Y,Z normalized)
    float o[3][3];   // per-view camera origin (unnormalized Z)
};

// --- camera matrix, mirroring jnp fp32 op order -----------------------------
__device__ __forceinline__ void cam_mat(const float* prm, float* Crow, float* O) {
    const float PI = 3.14159265358979323846f;
    float theta = prm[0] * PI / 180.0f;
    float e     = prm[1] * PI / 180.0f;
    float camy  = prm[3] * sinf(e);
    float lens  = prm[3] * cosf(e);
    float camx  = lens * cosf(theta);
    float camz  = lens * sinf(theta);

    float Zv[3] = { camx, camy, camz };
    float Yv[3] = { camy * cosf(theta + PI), lens, camy * sinf(theta + PI) };
    float Xv[3] = { Yv[1]*Zv[2] - Yv[2]*Zv[1],
                    Yv[2]*Zv[0] - Yv[0]*Zv[2],
                    Yv[0]*Zv[1] - Yv[1]*Zv[0] };

    float nx = sqrtf(Xv[0]*Xv[0] + Xv[1]*Xv[1] + Xv[2]*Xv[2]);
    float ny = sqrtf(Yv[0]*Yv[0] + Yv[1]*Yv[1] + Yv[2]*Yv[2]);
    float nz = sqrtf(Zv[0]*Zv[0] + Zv[1]*Zv[1] + Zv[2]*Zv[2]);
    for (int k = 0; k < 3; k++) {
        Crow[0*3 + k] = __fdiv_rn(Xv[k], nx);
        Crow[1*3 + k] = __fdiv_rn(Yv[k], ny);
        Crow[2*3 + k] = __fdiv_rn(Zv[k], nz);
        O[k] = Zv[k];
    }
}

// --- kernel A: per-block camera setup (incl. DP inverse) + per-point offsets
__global__ __launch_bounds__(256)
void proj_kernel(const float* __restrict__ coord,
                 const float* __restrict__ cams, int N) {
    __shared__ CamData cam;

    if (threadIdx.x == 0) {
        for (int i = 0; i < 3; i++)
            cam_mat(cams + i * 5, cam.c[i], cam.o[i]);

        double M[3][3];
        for (int r = 0; r < 3; r++)
            for (int k = 0; k < 3; k++)
                M[r][k] = (double)cam.c[0][k*3 + r];

        double det = M[0][0]*(M[1][1]*M[2][2] - M[1][2]*M[2][1])
                   - M[0][1]*(M[1][0]*M[2][2] - M[1][2]*M[2][0])
                   + M[0][2]*(M[1][0]*M[2][1] - M[1][1]*M[2][0]);
        double inv[3][3];
        inv[0][0] =  (M[1][1]*M[2][2] - M[1][2]*M[2][1]) / det;
        inv[0][1] =  (M[0][2]*M[2][1] - M[0][1]*M[2][2]) / det;
        inv[0][2] =  (M[0][1]*M[1][2] - M[0][2]*M[1][1]) / det;
        inv[1][0] =  (M[1][2]*M[2][0] - M[1][0]*M[2][2]) / det;
        inv[1][1] =  (M[0][0]*M[2][2] - M[0][2]*M[2][0]) / det;
        inv[1][2] =  (M[0][2]*M[1][0] - M[0][0]*M[1][2]) / det;
        inv[2][0] =  (M[1][0]*M[2][1] - M[1][1]*M[2][0]) / det;
        inv[2][1] =  (M[0][1]*M[2][0] - M[0][0]*M[2][1]) / det;
        inv[2][2] =  (M[0][0]*M[1][1] - M[0][1]*M[1][0]) / det;
        for (int k = 0; k < 3; k++)
            for (int j = 0; j < 3; j++)
                cam.B0[k*3 + j] = (float)inv[k][j];
    }
    __syncthreads();

    int p = blockIdx.x * blockDim.x + threadIdx.x;
    if (p >= N) return;

    float x = coord[p*3 + 0];
    float y = coord[p*3 + 1];
    float z = coord[p*3 + 2];

    float po[3];
    #pragma unroll
    for (int j = 0; j < 3; j++)
        po[j] = x * cam.B0[0*3 + j] + y * cam.B0[1*3 + j]
              + z * cam.B0[2*3 + j] + cam.o[0][j];

    const int   ds[4] = { 56, 28, 14, 7 };
    const int   Cs[4] = { 64, 128, 256, 512 };
    const float qi[4] = { 0.25f, 0.125f, 0.0625f, 0.03125f };  // d/224 exact pow2

    int off[12];
    #pragma unroll
    for (int i = 0; i < 3; i++) {
        float vx = po[0] - cam.o[i][0];
        float vy = po[1] - cam.o[i][1];
        float vz = po[2] - cam.o[i][2];
        const float* C = cam.c[i];
        float X  = vx*C[0] + vy*C[1] + vz*C[2];
        float Y  = vx*C[3] + vy*C[4] + vz*C[5];
        float Zc = vx*C[6] + vy*C[7] + vz*C[8];

        float negz = -Zc;
        float h = __fdiv_rn(248.0f * (-Y), negz) + 112.0f;
        float w = __fdiv_rn(248.0f * X,    negz) + 112.0f;
        h = fminf(fmaxf(h, 0.0f), 223.0f);
        w = fminf(fmaxf(w, 0.0f), 223.0f);

        #pragma unroll
        for (int s = 0; s < 4; s++) {
            int ih = (int)(h * qi[s]);
            int iw = (int)(w * qi[s]);
            off[i*4 + s] = (ih * ds[s] + iw) * Cs[s];
        }
    }
    int4* dst = reinterpret_cast<int4*>(g_off + p*12);
    dst[0] = make_int4(off[0], off[1], off[2],  off[3]);
    dst[1] = make_int4(off[4], off[5], off[6],  off[7]);
    dst[2] = make_int4(off[8], off[9], off[10], off[11]);
}

// channel -> (feature tensor, scale idx, local channel)
__device__ __forceinline__ void map_ch(int c, const float* f1, const float* f2,
                                       const float* f3, const float* f4,
                                       const float*& f, int& s, int& cl) {
    if (c < 64)       { s = 0; f = f1; cl = c; }
    else if (c < 192) { s = 1; f = f2; cl = c - 64; }
    else if (c < 448) { s = 2; f = f3; cl = c - 192; }
    else              { s = 3; f = f4; cl = c - 448; }
}

// window [sh, sh+4) over (A[0..3], N[0..2]) where N = neighbor quad's first 3
__device__ __forceinline__ void shiftwin(int sh, float4 A,
                                         float nx, float ny, float nz,
                                         float w[4]) {
    switch (sh) {
        case 0:  w[0]=A.x; w[1]=A.y; w[2]=A.z; w[3]=A.w; break;
        case 1:  w[0]=A.y; w[1]=A.z; w[2]=A.w; w[3]=nx;  break;
        case 2:  w[0]=A.z; w[1]=A.w; w[2]=nx;  w[3]=ny;  break;
        default: w[0]=A.w; w[1]=nx;  w[2]=ny;  w[3]=nz;  break;
    }
}

// --- kernel B: shuffle-assisted shifted-window gather, aligned STG.128 ------
__global__ __launch_bounds__(256, 6)
void gather_kernel(const float* __restrict__ f1, const float* __restrict__ f2,
                   const float* __restrict__ f3, const float* __restrict__ f4,
                   const float* __restrict__ coord, float* __restrict__ out) {
    unsigned p = blockIdx.x;
    int t = threadIdx.x;

    __shared__ int soff[12];
    if (t < 12) soff[t] = g_off[p*12 + t];
    __syncthreads();

    unsigned g = p * (unsigned)OUT_STRIDE;          // < 2^31
    int sh = (int)((4u - ((g + 3u) & 3u)) & 3u);    // g+3+sh ≡ 0 (mod 4)

    // all 256 threads run the main path (convergent shuffles); q clamped
    int q  = min(t, 239);
    int c4 = q * 4;

    const float* fa; int sa, cla;
    map_ch(c4, f1, f2, f3, f4, fa, sa, cla);

    float4 A0 = __ldg(reinterpret_cast<const float4*>(fa + soff[0 + sa] + cla));
    float4 A1 = __ldg(reinterpret_cast<const float4*>(fa + soff[4 + sa] + cla));
    float4 A2 = __ldg(reinterpret_cast<const float4*>(fa + soff[8 + sa] + cla));

    float n0x = 0.f, n0y = 0.f, n0z = 0.f;
    float n1x = 0.f, n1y = 0.f, n1z = 0.f;
    float n2x = 0.f, n2y = 0.f, n2z = 0.f;

    if (sh) {   // uniform branch (sh depends only on blockIdx)
        n0x = __shfl_down_sync(0xFFFFFFFFu, A0.x, 1);
        n0y = __shfl_down_sync(0xFFFFFFFFu, A0.y, 1);
        n0z = __shfl_down_sync(0xFFFFFFFFu, A0.z, 1);
        n1x = __shfl_down_sync(0xFFFFFFFFu, A1.x, 1);
        n1y = __shfl_down_sync(0xFFFFFFFFu, A1.y, 1);
        n1z = __shfl_down_sync(0xFFFFFFFFu, A1.z, 1);
        n2x = __shfl_down_sync(0xFFFFFFFFu, A2.x, 1);
        n2y = __shfl_down_sync(0xFFFFFFFFu, A2.y, 1);
        n2z = __shfl_down_sync(0xFFFFFFFFu, A2.z, 1);

        // lane 31: neighbor lives in the next warp -> direct load
        if ((t & 31) == 31 && t < 239) {
            const float* fb; int sb, clb;
            map_ch(c4 + 4, f1, f2, f3, f4, fb, sb, clb);
            float4 B0 = __ldg(reinterpret_cast<const float4*>(fb + soff[0 + sb] + clb));
            float4 B1 = __ldg(reinterpret_cast<const float4*>(fb + soff[4 + sb] + clb));
            float4 B2 = __ldg(reinterpret_cast<const float4*>(fb + soff[8 + sb] + clb));
            n0x = B0.x; n0y = B0.y; n0z = B0.z;
            n1x = B1.x; n1y = B1.y; n1z = B1.z;
            n2x = B2.x; n2y = B2.y; n2z = B2.z;
        }
    }

    float av[4], bv[4], dv[4];
    shiftwin(sh, A0, n0x, n0y, n0z, av);
    shiftwin(sh, A1, n1x, n1y, n1z, bv);
    shiftwin(sh, A2, n2x, n2y, n2z, dv);

    float mxv[4], mnv[4], sdv[4];
    #pragma unroll
    for (int k = 0; k < 4; k++) {
        float aa = av[k], bb = bv[k], dd = dv[k];
        mxv[k] = fmaxf(aa, fmaxf(bb, dd));
        float mn = (aa + bb + dd) * (1.0f / 3.0f);
        mnv[k] = mn;
        float da = aa - mn, db = bb - mn, dc = dd - mn;
        sdv[k] = sqrtf((da*da + db*db + dc*dc) * (1.0f / 3.0f));
    }

    bool store_ok = sh ? (t < 239) : (t < 240);
    if (store_ok) {
        float* base = out + (g + 3u + (unsigned)(sh + c4));
        *reinterpret_cast<float4*>(base)        = make_float4(mxv[0], mxv[1], mxv[2], mxv[3]);
        *reinterpret_cast<float4*>(base + 960)  = make_float4(mnv[0], mnv[1], mnv[2], mnv[3]);
        *reinterpret_cast<float4*>(base + 1920) = make_float4(sdv[0], sdv[1], sdv[2], sdv[3]);
    }

    if (t >= 240) {
        int h = t - 240;                       // 0..15
        if (sh && h < 4) {
            // edge channels: head [0, sh), tail [sh+956, 960)
            int ch = (h < sh) ? h : (956 + sh + (h - sh));
            const float* f; int ss, cl;
            map_ch(ch, f1, f2, f3, f4, f, ss, cl);
            float a = __ldg(f + soff[0 + ss] + cl);
            float b = __ldg(f + soff[4 + ss] + cl);
            float d = __ldg(f + soff[8 + ss] + cl);
            float mx = fmaxf(a, fmaxf(b, d));
            float mn = (a + b + d) * (1.0f / 3.0f);
            float da = a - mn, db = b - mn, dc = d - mn;
            float sd = sqrtf((da*da + db*db + dc*dc) * (1.0f / 3.0f));
            out[g + 3u + (unsigned)ch]    = mx;
            out[g + 963u + (unsigned)ch]  = mn;
            out[g + 1923u + (unsigned)ch] = sd;
        }
        if (h >= 8 && h < 11)                  // coord passthrough
            out[g + (unsigned)(h - 8)] = __ldg(coord + p*3 + (h - 8));
    }
}

extern "C" void kernel_launch(void* const* d_in, const int* in_sizes, int n_in,
                              void* d_out, int out_size) {
    const float* coord = (const float*)d_in[0];
    const float* cams  = (const float*)d_in[1];
    const float* f1    = (const float*)d_in[2];
    const float* f2    = (const float*)d_in[3];
    const float* f3    = (const float*)d_in[4];
    const float* f4    = (const float*)d_in[5];
    float* out = (float*)d_out;

    int N = in_sizes[0] / 3;

    proj_kernel<<<(N + 255) / 256, 256>>>(coord, cams, N);
    gather_kernel<<<N, 256>>>(f1, f2, f3, f4, coord, out);
}